// round 3
// baseline (speedup 1.0000x reference)
#include <cuda_runtime.h>
#include <math.h>

// ---------------- problem constants ----------------
#define B    1024
#define LU   200
#define LH   50
#define D    768        // = 192 float4
#define XDIM 1552       // 768 + 768 + 16
#define HID  512
#define KDIM 1552

// ---------------- scratch (__device__ globals; no allocation allowed) ------
__device__ float g_x[B * XDIM];   // fc1 input  [1024,1552]
__device__ float g_y[B * HID];    // fc1 output [1024,512]
__device__ float g_mu[HID];
__device__ float g_rstd[HID];

// ---------------- kernel 1: masked means -> g_x[:, 0:1536] ----------------
// grid (B, 2), block 192. blockIdx.y==0 -> user (768 cols), 1 -> hashtag.
__global__ __launch_bounds__(192) void mean_kernel(
    const float* __restrict__ uf, const int* __restrict__ ulen,
    const float* __restrict__ hf, const int* __restrict__ hlen)
{
    int b = blockIdx.x;
    int t = threadIdx.x;               // 0..191, one float4 column each
    const float4* p;
    int len, off;
    if (blockIdx.y == 0) {
        p   = (const float4*)uf + (size_t)b * LU * (D / 4) + t;
        len = ulen[b];
        off = 0;
    } else {
        p   = (const float4*)hf + (size_t)b * LH * (D / 4) + t;
        len = hlen[b];
        off = D;
    }

    float4 a0 = make_float4(0.f, 0.f, 0.f, 0.f);
    float4 a1 = make_float4(0.f, 0.f, 0.f, 0.f);
    int l = 0;
    for (; l + 1 < len; l += 2) {
        float4 v0 = p[(size_t)l * (D / 4)];
        float4 v1 = p[(size_t)(l + 1) * (D / 4)];
        a0.x += v0.x; a0.y += v0.y; a0.z += v0.z; a0.w += v0.w;
        a1.x += v1.x; a1.y += v1.y; a1.z += v1.z; a1.w += v1.w;
    }
    if (l < len) {
        float4 v0 = p[(size_t)l * (D / 4)];
        a0.x += v0.x; a0.y += v0.y; a0.z += v0.z; a0.w += v0.w;
    }
    float inv = 1.0f / (float)len;
    float4 o = make_float4((a0.x + a1.x) * inv, (a0.y + a1.y) * inv,
                           (a0.z + a1.z) * inv, (a0.w + a1.w) * inv);
    *(float4*)(g_x + (size_t)b * XDIM + off + t * 4) = o;
}

// ---------------- kernel 2: NeuMF tower -> g_x[:, 1536:1552] ----------------
// grid 4, block 256 (one thread per batch row).
__global__ __launch_bounds__(256) void ncf_kernel(
    const int* __restrict__ users, const int* __restrict__ items,
    const float* __restrict__ u_mf, const float* __restrict__ i_mf,
    const float* __restrict__ u_mlp, const float* __restrict__ i_mlp,
    const float* __restrict__ w0, const float* __restrict__ b0,
    const float* __restrict__ w1, const float* __restrict__ b1,
    const float* __restrict__ w2, const float* __restrict__ b2)
{
    __shared__ float s[16 * 32 + 32 + 32 * 16 + 16 + 16 * 8 + 8];  // 1208
    float* sw0 = s;
    float* sb0 = sw0 + 16 * 32;
    float* sw1 = sb0 + 32;
    float* sb1 = sw1 + 32 * 16;
    float* sw2 = sb1 + 16;
    float* sb2 = sw2 + 16 * 8;

    int t = threadIdx.x;
    for (int i = t; i < 512; i += 256) sw0[i] = w0[i];
    for (int i = t; i < 512; i += 256) sw1[i] = w1[i];
    for (int i = t; i < 128; i += 256) sw2[i] = w2[i];
    if (t < 32) sb0[t] = b0[t];
    if (t < 16) sb1[t] = b1[t];
    if (t < 8)  sb2[t] = b2[t];
    __syncthreads();

    int b  = blockIdx.x * 256 + t;
    int u  = users[b];
    int it = items[b];

    float h16[16];
#pragma unroll
    for (int k = 0; k < 8; k++) {
        h16[k]     = u_mlp[u * 8 + k];
        h16[8 + k] = i_mlp[it * 8 + k];
    }
    float h32[32];
#pragma unroll
    for (int j = 0; j < 32; j++) {
        float acc = sb0[j];
#pragma unroll
        for (int k = 0; k < 16; k++) acc += h16[k] * sw0[k * 32 + j];
        h32[j] = fmaxf(acc, 0.f);
    }
    float g16[16];
#pragma unroll
    for (int j = 0; j < 16; j++) {
        float acc = sb1[j];
#pragma unroll
        for (int k = 0; k < 32; k++) acc += h32[k] * sw1[k * 16 + j];
        g16[j] = fmaxf(acc, 0.f);
    }
    float h8[8];
#pragma unroll
    for (int j = 0; j < 8; j++) {
        float acc = sb2[j];
#pragma unroll
        for (int k = 0; k < 16; k++) acc += g16[k] * sw2[k * 8 + j];
        h8[j] = fmaxf(acc, 0.f);
    }

    float* xp = g_x + (size_t)b * XDIM + 2 * D;   // cols 1536..1551
#pragma unroll
    for (int j = 0; j < 8; j++) xp[j] = h8[j];
#pragma unroll
    for (int j = 0; j < 8; j++) xp[8 + j] = u_mf[u * 8 + j] * i_mf[it * 8 + j];
}

// ---------------- kernel 3: fc1 GEMM  g_y = g_x @ W + bias ----------------
// BM=64, BN=32, BK=16, 128 threads, 4x4 register tile. grid (16,16).
#define BM 64
#define BN 32
#define BK 16
__global__ __launch_bounds__(128) void gemm_kernel(
    const float* __restrict__ W, const float* __restrict__ bias)
{
    __shared__ float As[BK][BM];   // A stored k-major (transposed)
    __shared__ float Bs[BK][BN];

    int tid = threadIdx.x;         // 128
    int tx  = tid & 7;             // 0..7  -> n group
    int ty  = tid >> 3;            // 0..15 -> m group
    int m0  = blockIdx.y * BM;
    int n0  = blockIdx.x * BN;

    float acc[4][4];
#pragma unroll
    for (int i = 0; i < 4; i++)
#pragma unroll
        for (int j = 0; j < 4; j++) acc[i][j] = 0.f;

    for (int k0 = 0; k0 < KDIM; k0 += BK) {
        // A tile: 64x16 = 256 float4; 2 per thread
#pragma unroll
        for (int i = 0; i < 2; i++) {
            int idx = tid + i * 128;          // 0..255
            int row = idx >> 2;               // 0..63
            int c4  = idx & 3;                // 0..3
            float4 v = *(const float4*)(g_x + (size_t)(m0 + row) * KDIM + k0 + c4 * 4);
            As[c4 * 4 + 0][row] = v.x;
            As[c4 * 4 + 1][row] = v.y;
            As[c4 * 4 + 2][row] = v.z;
            As[c4 * 4 + 3][row] = v.w;
        }
        // B tile: 16x32 = 128 float4; 1 per thread
        {
            int row = tid >> 3;               // 0..15
            int c4  = tid & 7;                // 0..7
            float4 v = *(const float4*)(W + (size_t)(k0 + row) * HID + n0 + c4 * 4);
            *(float4*)&Bs[row][c4 * 4] = v;
        }
        __syncthreads();

#pragma unroll
        for (int kk = 0; kk < BK; kk++) {
            float a[4], bb[4];
            *(float4*)a  = *(const float4*)&As[kk][ty * 4];
            *(float4*)bb = *(const float4*)&Bs[kk][tx * 4];
#pragma unroll
            for (int i = 0; i < 4; i++)
#pragma unroll
                for (int j = 0; j < 4; j++) acc[i][j] += a[i] * bb[j];
        }
        __syncthreads();
    }

    int n = n0 + tx * 4;
    float4 bv = *(const float4*)(bias + n);
#pragma unroll
    for (int i = 0; i < 4; i++) {
        int m = m0 + ty * 4 + i;
        float4 o = make_float4(acc[i][0] + bv.x, acc[i][1] + bv.y,
                               acc[i][2] + bv.z, acc[i][3] + bv.w);
        *(float4*)(g_y + (size_t)m * HID + n) = o;
    }
}

// ---------------- kernel 4: batch-norm statistics ----------------
// grid 4, block 128: one thread per column.
__global__ __launch_bounds__(128) void bn_stats_kernel()
{
    int col = blockIdx.x * 128 + threadIdx.x;
    float s = 0.f, s2 = 0.f;
#pragma unroll 8
    for (int r = 0; r < B; r++) {
        float v = g_y[(size_t)r * HID + col];
        s  += v;
        s2 += v * v;
    }
    float mu  = s * (1.0f / B);
    float var = s2 * (1.0f / B) - mu * mu;
    g_mu[col]   = mu;
    g_rstd[col] = rsqrtf(var + 1e-5f);
}

// ---------------- kernel 5: BN apply + relu + fc3 + sigmoid ----------------
// grid B, block 128.
__global__ __launch_bounds__(128) void final_kernel(
    const float* __restrict__ gamma, const float* __restrict__ beta,
    const float* __restrict__ w3, const float* __restrict__ b3,
    float* __restrict__ out)
{
    int b = blockIdx.x;
    int t = threadIdx.x;
    float acc = 0.f;
#pragma unroll
    for (int j = t; j < HID; j += 128) {
        float v = (g_y[(size_t)b * HID + j] - g_mu[j]) * g_rstd[j] * gamma[j] + beta[j];
        v = fmaxf(v, 0.f);
        acc += v * w3[j];
    }
#pragma unroll
    for (int o = 16; o; o >>= 1) acc += __shfl_down_sync(0xffffffff, acc, o);
    __shared__ float red[4];
    if ((t & 31) == 0) red[t >> 5] = acc;
    __syncthreads();
    if (t == 0) {
        float tot = red[0] + red[1] + red[2] + red[3] + b3[0];
        out[b] = 1.0f / (1.0f + expf(-tot));
    }
}

// ---------------- launch ----------------
extern "C" void kernel_launch(void* const* d_in, const int* in_sizes, int n_in,
                              void* d_out, int out_size)
{
    (void)in_sizes; (void)n_in; (void)out_size;
    // metadata order (= setup_inputs dict order):
    // 0 sign, 1 user_features, 2 user_lens, 3 hashtag_features, 4 hashtag_lens,
    // 5 users, 6 items, 7 fc1_w, 8 fc1_b, 9 bn_gamma, 10 bn_beta, 11 fc3_w,
    // 12 fc3_b, 13 u_mf, 14 i_mf, 15 u_mlp, 16 i_mlp,
    // 17 mlp_w0, 18 mlp_b0, 19 mlp_w1, 20 mlp_b1, 21 mlp_w2, 22 mlp_b2
    const float* uf    = (const float*)d_in[1];
    const int*   ulen  = (const int*)  d_in[2];
    const float* hf    = (const float*)d_in[3];
    const int*   hlen  = (const int*)  d_in[4];
    const int*   users = (const int*)  d_in[5];
    const int*   items = (const int*)  d_in[6];
    const float* fc1_w = (const float*)d_in[7];
    const float* fc1_b = (const float*)d_in[8];
    const float* gamma = (const float*)d_in[9];
    const float* beta  = (const float*)d_in[10];
    const float* fc3_w = (const float*)d_in[11];
    const float* fc3_b = (const float*)d_in[12];
    const float* u_mf  = (const float*)d_in[13];
    const float* i_mf  = (const float*)d_in[14];
    const float* u_mlp = (const float*)d_in[15];
    const float* i_mlp = (const float*)d_in[16];
    const float* w0    = (const float*)d_in[17];
    const float* b0    = (const float*)d_in[18];
    const float* w1    = (const float*)d_in[19];
    const float* b1    = (const float*)d_in[20];
    const float* w2    = (const float*)d_in[21];
    const float* b2    = (const float*)d_in[22];
    float* out = (float*)d_out;

    dim3 gm(B, 2);
    mean_kernel<<<gm, 192>>>(uf, ulen, hf, hlen);
    ncf_kernel<<<4, 256>>>(users, items, u_mf, i_mf, u_mlp, i_mlp,
                           w0, b0, w1, b1, w2, b2);
    dim3 gg(HID / BN, B / BM);   // (16,16)
    gemm_kernel<<<gg, 128>>>(fc1_w, fc1_b);
    bn_stats_kernel<<<4, 128>>>();
    final_kernel<<<B, 128>>>(gamma, beta, fc3_w, fc3_b, out);
}

// round 4
// speedup vs baseline: 1.1549x; 1.1549x over previous
#include <cuda_runtime.h>
#include <math.h>
#include <stdint.h>

// ---------------- problem constants ----------------
#define B    1024
#define LU   200
#define LH   50
#define D    768        // = 192 float4
#define XDIM 1552       // 768 + 768 + 16
#define HID  512
#define KDIM 1552

// ---------------- scratch (__device__ globals; no allocation allowed) ------
__device__ float g_x[B * XDIM];     // fc1 input  [1024,1552]
__device__ float g_y[B * HID];      // fc1 output [1024,512]
__device__ float g_psum[16][HID];   // per-m-tile column sums
__device__ float g_psq [16][HID];   // per-m-tile column sums of squares
__device__ float g_mu[HID];
__device__ float g_rstd[HID];

// ---------------- kernel 1: masked means -> g_x[:, 0:1536] ----------------
// grid (B, 2), block 192. blockIdx.y==0 -> user (768 cols), 1 -> hashtag.
__global__ __launch_bounds__(192) void mean_kernel(
    const float* __restrict__ uf, const int* __restrict__ ulen,
    const float* __restrict__ hf, const int* __restrict__ hlen)
{
    int b = blockIdx.x;
    int t = threadIdx.x;               // 0..191, one float4 column each
    const float4* p;
    int len, off;
    if (blockIdx.y == 0) {
        p   = (const float4*)uf + (size_t)b * LU * (D / 4) + t;
        len = ulen[b];
        off = 0;
    } else {
        p   = (const float4*)hf + (size_t)b * LH * (D / 4) + t;
        len = hlen[b];
        off = D;
    }

    float4 a0 = make_float4(0.f, 0.f, 0.f, 0.f);
    float4 a1 = make_float4(0.f, 0.f, 0.f, 0.f);
    float4 a2 = make_float4(0.f, 0.f, 0.f, 0.f);
    float4 a3 = make_float4(0.f, 0.f, 0.f, 0.f);
    int l = 0;
    for (; l + 3 < len; l += 4) {
        float4 v0 = p[(size_t)(l + 0) * (D / 4)];
        float4 v1 = p[(size_t)(l + 1) * (D / 4)];
        float4 v2 = p[(size_t)(l + 2) * (D / 4)];
        float4 v3 = p[(size_t)(l + 3) * (D / 4)];
        a0.x += v0.x; a0.y += v0.y; a0.z += v0.z; a0.w += v0.w;
        a1.x += v1.x; a1.y += v1.y; a1.z += v1.z; a1.w += v1.w;
        a2.x += v2.x; a2.y += v2.y; a2.z += v2.z; a2.w += v2.w;
        a3.x += v3.x; a3.y += v3.y; a3.z += v3.z; a3.w += v3.w;
    }
    for (; l < len; l++) {
        float4 v0 = p[(size_t)l * (D / 4)];
        a0.x += v0.x; a0.y += v0.y; a0.z += v0.z; a0.w += v0.w;
    }
    float inv = 1.0f / (float)len;
    float4 o = make_float4((a0.x + a1.x + a2.x + a3.x) * inv,
                           (a0.y + a1.y + a2.y + a3.y) * inv,
                           (a0.z + a1.z + a2.z + a3.z) * inv,
                           (a0.w + a1.w + a2.w + a3.w) * inv);
    *(float4*)(g_x + (size_t)b * XDIM + off + t * 4) = o;
}

// ---------------- kernel 2: NeuMF tower -> g_x[:, 1536:1552] ----------------
// grid 4, block 256 (one thread per batch row).
__global__ __launch_bounds__(256) void ncf_kernel(
    const int* __restrict__ users, const int* __restrict__ items,
    const float* __restrict__ u_mf, const float* __restrict__ i_mf,
    const float* __restrict__ u_mlp, const float* __restrict__ i_mlp,
    const float* __restrict__ w0, const float* __restrict__ b0,
    const float* __restrict__ w1, const float* __restrict__ b1,
    const float* __restrict__ w2, const float* __restrict__ b2)
{
    __shared__ float s[16 * 32 + 32 + 32 * 16 + 16 + 16 * 8 + 8];  // 1208
    float* sw0 = s;
    float* sb0 = sw0 + 16 * 32;
    float* sw1 = sb0 + 32;
    float* sb1 = sw1 + 32 * 16;
    float* sw2 = sb1 + 16;
    float* sb2 = sw2 + 16 * 8;

    int t = threadIdx.x;
    for (int i = t; i < 512; i += 256) sw0[i] = w0[i];
    for (int i = t; i < 512; i += 256) sw1[i] = w1[i];
    for (int i = t; i < 128; i += 256) sw2[i] = w2[i];
    if (t < 32) sb0[t] = b0[t];
    if (t < 16) sb1[t] = b1[t];
    if (t < 8)  sb2[t] = b2[t];
    __syncthreads();

    int b  = blockIdx.x * 256 + t;
    int u  = users[b];
    int it = items[b];

    float h16[16];
#pragma unroll
    for (int k = 0; k < 8; k++) {
        h16[k]     = u_mlp[u * 8 + k];
        h16[8 + k] = i_mlp[it * 8 + k];
    }
    float h32[32];
#pragma unroll
    for (int j = 0; j < 32; j++) {
        float acc = sb0[j];
#pragma unroll
        for (int k = 0; k < 16; k++) acc += h16[k] * sw0[k * 32 + j];
        h32[j] = fmaxf(acc, 0.f);
    }
    float g16[16];
#pragma unroll
    for (int j = 0; j < 16; j++) {
        float acc = sb1[j];
#pragma unroll
        for (int k = 0; k < 32; k++) acc += h32[k] * sw1[k * 16 + j];
        g16[j] = fmaxf(acc, 0.f);
    }
    float h8[8];
#pragma unroll
    for (int j = 0; j < 8; j++) {
        float acc = sb2[j];
#pragma unroll
        for (int k = 0; k < 16; k++) acc += g16[k] * sw2[k * 8 + j];
        h8[j] = fmaxf(acc, 0.f);
    }

    float* xp = g_x + (size_t)b * XDIM + 2 * D;   // cols 1536..1551
#pragma unroll
    for (int j = 0; j < 8; j++) xp[j] = h8[j];
#pragma unroll
    for (int j = 0; j < 8; j++) xp[8 + j] = u_mf[u * 8 + j] * i_mf[it * 8 + j];
}

// ---- packed fp32x2 FMA (sm_10x; ptxas never auto-fuses this) ----
__device__ __forceinline__ void fma_f32x2(uint64_t& d, uint64_t a, uint64_t b) {
    asm("fma.rn.f32x2 %0, %1, %2, %0;" : "+l"(d) : "l"(a), "l"(b));
}
__device__ __forceinline__ uint64_t dup_f32(float a) {
    uint64_t r;
    asm("mov.b64 %0, {%1, %1};" : "=l"(r) : "f"(a));
    return r;
}

// ---------------- kernel 3: fc1 GEMM  g_y = g_x @ W + bias ----------------
// BM=64, BN=32, BK=16, 128 threads, 4x4 register tile (packed f32x2 FMA).
// Also emits per-(m-tile, column) partial sums/sumsq for batch norm.
#define BM 64
#define BN 32
#define BK 16
__global__ __launch_bounds__(128) void gemm_kernel(
    const float* __restrict__ W, const float* __restrict__ bias)
{
    __shared__ float As[BK][BM];   // A stored k-major (transposed)
    __shared__ float Bs[BK][BN];
    __shared__ float rsum[16][BN];
    __shared__ float rsq [16][BN];

    int tid = threadIdx.x;         // 128
    int tx  = tid & 7;             // 0..7  -> n group
    int ty  = tid >> 3;            // 0..15 -> m group
    int m0  = blockIdx.y * BM;
    int n0  = blockIdx.x * BN;

    uint64_t acc2[4][2];           // 4 rows x 2 packed (f32x2) columns
#pragma unroll
    for (int i = 0; i < 4; i++) { acc2[i][0] = 0ull; acc2[i][1] = 0ull; }

    for (int k0 = 0; k0 < KDIM; k0 += BK) {
        // A tile: 64x16 = 256 float4; 2 per thread
#pragma unroll
        for (int i = 0; i < 2; i++) {
            int idx = tid + i * 128;          // 0..255
            int row = idx >> 2;               // 0..63
            int c4  = idx & 3;                // 0..3
            float4 v = *(const float4*)(g_x + (size_t)(m0 + row) * KDIM + k0 + c4 * 4);
            As[c4 * 4 + 0][row] = v.x;
            As[c4 * 4 + 1][row] = v.y;
            As[c4 * 4 + 2][row] = v.z;
            As[c4 * 4 + 3][row] = v.w;
        }
        // B tile: 16x32 = 128 float4; 1 per thread
        {
            int row = tid >> 3;               // 0..15
            int c4  = tid & 7;                // 0..7
            float4 v = *(const float4*)(W + (size_t)(k0 + row) * HID + n0 + c4 * 4);
            *(float4*)&Bs[row][c4 * 4] = v;
        }
        __syncthreads();

#pragma unroll
        for (int kk = 0; kk < BK; kk++) {
            float a[4];
            *(float4*)a = *(const float4*)&As[kk][ty * 4];
            // Bs row is 16B-aligned at tx*4: reinterpret as two packed f32x2
            uint64_t b01 = *(const uint64_t*)&Bs[kk][tx * 4 + 0];
            uint64_t b23 = *(const uint64_t*)&Bs[kk][tx * 4 + 2];
#pragma unroll
            for (int i = 0; i < 4; i++) {
                uint64_t aa = dup_f32(a[i]);
                fma_f32x2(acc2[i][0], aa, b01);
                fma_f32x2(acc2[i][1], aa, b23);
            }
        }
        __syncthreads();
    }

    // unpack, add bias, store, and accumulate per-column sums over this tile
    int n = n0 + tx * 4;
    float4 bv = *(const float4*)(bias + n);
    float cs[4]  = {0.f, 0.f, 0.f, 0.f};
    float cs2[4] = {0.f, 0.f, 0.f, 0.f};
#pragma unroll
    for (int i = 0; i < 4; i++) {
        float2 p01 = *(float2*)&acc2[i][0];
        float2 p23 = *(float2*)&acc2[i][1];
        float v0 = p01.x + bv.x;
        float v1 = p01.y + bv.y;
        float v2 = p23.x + bv.z;
        float v3 = p23.y + bv.w;
        int m = m0 + ty * 4 + i;
        *(float4*)(g_y + (size_t)m * HID + n) = make_float4(v0, v1, v2, v3);
        cs[0] += v0; cs[1] += v1; cs[2] += v2; cs[3] += v3;
        cs2[0] += v0 * v0; cs2[1] += v1 * v1; cs2[2] += v2 * v2; cs2[3] += v3 * v3;
    }
#pragma unroll
    for (int j = 0; j < 4; j++) {
        rsum[ty][tx * 4 + j] = cs[j];
        rsq [ty][tx * 4 + j] = cs2[j];
    }
    __syncthreads();
    if (tid < BN) {                 // one thread per column of this tile
        float s = 0.f, q = 0.f;
#pragma unroll
        for (int r = 0; r < 16; r++) { s += rsum[r][tid]; q += rsq[r][tid]; }
        g_psum[blockIdx.y][n0 + tid] = s;
        g_psq [blockIdx.y][n0 + tid] = q;
    }
}

// ---------------- kernel 4: batch-norm finalize (tiny) ----------------
// grid 2, block 256: one thread per column; reduce 16 tile-partials.
__global__ __launch_bounds__(256) void bn_finalize_kernel()
{
    int col = blockIdx.x * 256 + threadIdx.x;
    float s = 0.f, q = 0.f;
#pragma unroll
    for (int r = 0; r < 16; r++) {
        s += g_psum[r][col];
        q += g_psq [r][col];
    }
    float mu  = s * (1.0f / B);
    float var = q * (1.0f / B) - mu * mu;
    g_mu[col]   = mu;
    g_rstd[col] = rsqrtf(var + 1e-5f);
}

// ---------------- kernel 5: BN apply + relu + fc3 + sigmoid ----------------
// grid B, block 128.
__global__ __launch_bounds__(128) void final_kernel(
    const float* __restrict__ gamma, const float* __restrict__ beta,
    const float* __restrict__ w3, const float* __restrict__ b3,
    float* __restrict__ out)
{
    int b = blockIdx.x;
    int t = threadIdx.x;
    float acc = 0.f;
#pragma unroll
    for (int j = t; j < HID; j += 128) {
        float v = (g_y[(size_t)b * HID + j] - g_mu[j]) * g_rstd[j] * gamma[j] + beta[j];
        v = fmaxf(v, 0.f);
        acc += v * w3[j];
    }
#pragma unroll
    for (int o = 16; o; o >>= 1) acc += __shfl_down_sync(0xffffffff, acc, o);
    __shared__ float red[4];
    if ((t & 31) == 0) red[t >> 5] = acc;
    __syncthreads();
    if (t == 0) {
        float tot = red[0] + red[1] + red[2] + red[3] + b3[0];
        out[b] = 1.0f / (1.0f + expf(-tot));
    }
}

// ---------------- launch ----------------
extern "C" void kernel_launch(void* const* d_in, const int* in_sizes, int n_in,
                              void* d_out, int out_size)
{
    (void)in_sizes; (void)n_in; (void)out_size;
    const float* uf    = (const float*)d_in[1];
    const int*   ulen  = (const int*)  d_in[2];
    const float* hf    = (const float*)d_in[3];
    const int*   hlen  = (const int*)  d_in[4];
    const int*   users = (const int*)  d_in[5];
    const int*   items = (const int*)  d_in[6];
    const float* fc1_w = (const float*)d_in[7];
    const float* fc1_b = (const float*)d_in[8];
    const float* gamma = (const float*)d_in[9];
    const float* beta  = (const float*)d_in[10];
    const float* fc3_w = (const float*)d_in[11];
    const float* fc3_b = (const float*)d_in[12];
    const float* u_mf  = (const float*)d_in[13];
    const float* i_mf  = (const float*)d_in[14];
    const float* u_mlp = (const float*)d_in[15];
    const float* i_mlp = (const float*)d_in[16];
    const float* w0    = (const float*)d_in[17];
    const float* b0    = (const float*)d_in[18];
    const float* w1    = (const float*)d_in[19];
    const float* b1    = (const float*)d_in[20];
    const float* w2    = (const float*)d_in[21];
    const float* b2    = (const float*)d_in[22];
    float* out = (float*)d_out;

    dim3 gm(B, 2);
    mean_kernel<<<gm, 192>>>(uf, ulen, hf, hlen);
    ncf_kernel<<<4, 256>>>(users, items, u_mf, i_mf, u_mlp, i_mlp,
                           w0, b0, w1, b1, w2, b2);
    dim3 gg(HID / BN, B / BM);   // (16,16)
    gemm_kernel<<<gg, 128>>>(fc1_w, fc1_b);
    bn_finalize_kernel<<<2, 256>>>();
    final_kernel<<<B, 128>>>(gamma, beta, fc3_w, fc3_b, out);
}